// round 5
// baseline (speedup 1.0000x reference)
#include <cuda_runtime.h>
#include <cuda_bf16.h>
#include <cstdint>

#define B_  8
#define S_  1024
#define H_  1024
#define NH_ 16
#define HD_ 64
#define MROWS (B_ * S_)

// Scratch: Q, K, V projections and attention output (each 32 MB).
__device__ float g_Q[MROWS * H_];
__device__ float g_K[MROWS * H_];
__device__ float g_V[MROWS * H_];
__device__ float g_A[MROWS * H_];

__device__ __forceinline__ uint32_t smem_u32(const void* p) {
    uint32_t a;
    asm("{ .reg .u64 t; cvta.to.shared.u64 t, %1; cvt.u32.u64 %0, t; }"
        : "=r"(a) : "l"(p));
    return a;
}

#define LDMX4(r0, r1, r2, r3, addr) \
    asm volatile("ldmatrix.sync.aligned.m8n8.x4.shared.b16 {%0,%1,%2,%3}, [%4];" \
                 : "=r"(r0), "=r"(r1), "=r"(r2), "=r"(r3) : "r"(addr))

#define MMA16816(d, a, b) \
    asm volatile("mma.sync.aligned.m16n8k16.row.col.f32.bf16.bf16.f32 " \
                 "{%0,%1,%2,%3}, {%4,%5,%6,%7}, {%8,%9}, {%0,%1,%2,%3};" \
                 : "+f"((d)[0]), "+f"((d)[1]), "+f"((d)[2]), "+f"((d)[3]) \
                 : "r"((a)[0]), "r"((a)[1]), "r"((a)[2]), "r"((a)[3]), \
                   "r"((b)[0]), "r"((b)[1]))

// ===========================================================================
// bf16 mma.sync split-precision GEMM (unchanged from R4, known-good).
// C[m,n] = sum_k A[m,k]*W[n,k] + bias[n]; 128x128 tile, BK=32, 8 warps.
// ===========================================================================
#define LDSROW 40   // bf16 elems per smem row (32 + 8 pad) -> 80 bytes

__global__ __launch_bounds__(256, 1)
void gemm_tc(const float* __restrict__ A, const float* __restrict__ W,
             const float* __restrict__ bias, float* __restrict__ C)
{
    __shared__ __nv_bfloat16 sAh[128 * LDSROW];
    __shared__ __nv_bfloat16 sAl[128 * LDSROW];
    __shared__ __nv_bfloat16 sWh[128 * LDSROW];
    __shared__ __nv_bfloat16 sWl[128 * LDSROW];

    const int tid  = threadIdx.x;
    const int wid  = tid >> 5;
    const int lane = tid & 31;
    const int wm   = wid & 1;
    const int wn   = wid >> 1;
    const int bm0  = blockIdx.y * 128;
    const int bn0  = blockIdx.x * 128;

    const uint32_t bAh = smem_u32(sAh);
    const uint32_t bAl = smem_u32(sAl);
    const uint32_t bWh = smem_u32(sWh);
    const uint32_t bWl = smem_u32(sWl);

    const uint32_t aLOff = (uint32_t)((wm * 64 + (lane & 15)) * (LDSROW * 2) + (lane >> 4) * 16);
    const uint32_t bLOff = (uint32_t)((wn * 32 + ((lane >> 4) & 1) * 8 + (lane & 7)) * (LDSROW * 2)
                                      + ((lane >> 3) & 1) * 16);

    int gRow[4], gC4[4];
#pragma unroll
    for (int i = 0; i < 4; i++) { int s = tid + i * 256; gRow[i] = s >> 3; gC4[i] = s & 7; }

    float acc[4][4][4];
#pragma unroll
    for (int mi = 0; mi < 4; mi++)
#pragma unroll
        for (int nj = 0; nj < 4; nj++)
#pragma unroll
            for (int e = 0; e < 4; e++) acc[mi][nj][e] = 0.f;

    float4 ra[4], rw[4];
#pragma unroll
    for (int i = 0; i < 4; i++) {
        ra[i] = *(const float4*)(A + (size_t)(bm0 + gRow[i]) * H_ + gC4[i] * 4);
        rw[i] = *(const float4*)(W + (size_t)(bn0 + gRow[i]) * H_ + gC4[i] * 4);
    }

    for (int c = 0; c < 32; c++) {
#pragma unroll
        for (int i = 0; i < 4; i++) {
            const int off = gRow[i] * LDSROW + gC4[i] * 4;
            float4 a4 = ra[i], w4 = rw[i];
            __nv_bfloat162 ah01 = __float22bfloat162_rn(make_float2(a4.x, a4.y));
            __nv_bfloat162 ah23 = __float22bfloat162_rn(make_float2(a4.z, a4.w));
            __nv_bfloat162 al01 = __float22bfloat162_rn(make_float2(
                a4.x - __bfloat162float(ah01.x), a4.y - __bfloat162float(ah01.y)));
            __nv_bfloat162 al23 = __float22bfloat162_rn(make_float2(
                a4.z - __bfloat162float(ah23.x), a4.w - __bfloat162float(ah23.y)));
            *(__nv_bfloat162*)(sAh + off)     = ah01;
            *(__nv_bfloat162*)(sAh + off + 2) = ah23;
            *(__nv_bfloat162*)(sAl + off)     = al01;
            *(__nv_bfloat162*)(sAl + off + 2) = al23;

            __nv_bfloat162 wh01 = __float22bfloat162_rn(make_float2(w4.x, w4.y));
            __nv_bfloat162 wh23 = __float22bfloat162_rn(make_float2(w4.z, w4.w));
            __nv_bfloat162 wl01 = __float22bfloat162_rn(make_float2(
                w4.x - __bfloat162float(wh01.x), w4.y - __bfloat162float(wh01.y)));
            __nv_bfloat162 wl23 = __float22bfloat162_rn(make_float2(
                w4.z - __bfloat162float(wh23.x), w4.w - __bfloat162float(wh23.y)));
            *(__nv_bfloat162*)(sWh + off)     = wh01;
            *(__nv_bfloat162*)(sWh + off + 2) = wh23;
            *(__nv_bfloat162*)(sWl + off)     = wl01;
            *(__nv_bfloat162*)(sWl + off + 2) = wl23;
        }
        __syncthreads();

        if (c < 31) {
            const int k0 = (c + 1) * 32;
#pragma unroll
            for (int i = 0; i < 4; i++) {
                ra[i] = *(const float4*)(A + (size_t)(bm0 + gRow[i]) * H_ + k0 + gC4[i] * 4);
                rw[i] = *(const float4*)(W + (size_t)(bn0 + gRow[i]) * H_ + k0 + gC4[i] * 4);
            }
        }

#pragma unroll
        for (int ks = 0; ks < 2; ks++) {
            const uint32_t kb = (uint32_t)(ks * 32);
            uint32_t ah[4][4], al[4][4];
#pragma unroll
            for (int mi = 0; mi < 4; mi++) {
                const uint32_t rowb = (uint32_t)(mi * 16 * LDSROW * 2) + aLOff + kb;
                LDMX4(ah[mi][0], ah[mi][1], ah[mi][2], ah[mi][3], bAh + rowb);
                LDMX4(al[mi][0], al[mi][1], al[mi][2], al[mi][3], bAl + rowb);
            }
            uint32_t bh[4][2], bl[4][2];
#pragma unroll
            for (int pr = 0; pr < 2; pr++) {
                const uint32_t rowb = (uint32_t)(pr * 16 * LDSROW * 2) + bLOff + kb;
                LDMX4(bh[pr * 2][0], bh[pr * 2][1], bh[pr * 2 + 1][0], bh[pr * 2 + 1][1], bWh + rowb);
                LDMX4(bl[pr * 2][0], bl[pr * 2][1], bl[pr * 2 + 1][0], bl[pr * 2 + 1][1], bWl + rowb);
            }
#pragma unroll
            for (int mi = 0; mi < 4; mi++)
#pragma unroll
                for (int nj = 0; nj < 4; nj++) {
                    MMA16816(acc[mi][nj], ah[mi], bh[nj]);
                    MMA16816(acc[mi][nj], al[mi], bh[nj]);
                    MMA16816(acc[mi][nj], ah[mi], bl[nj]);
                }
        }
        __syncthreads();
    }

#pragma unroll
    for (int mi = 0; mi < 4; mi++) {
        const int r0 = bm0 + wm * 64 + mi * 16 + (lane >> 2);
#pragma unroll
        for (int nj = 0; nj < 4; nj++) {
            const int col = bn0 + wn * 32 + nj * 8 + (lane & 3) * 2;
            const float b0 = bias[col], b1 = bias[col + 1];
            float2 o0 = make_float2(acc[mi][nj][0] + b0, acc[mi][nj][1] + b1);
            float2 o1 = make_float2(acc[mi][nj][2] + b0, acc[mi][nj][3] + b1);
            *(float2*)(C + (size_t)r0 * H_ + col)       = o0;
            *(float2*)(C + (size_t)(r0 + 8) * H_ + col) = o1;
        }
    }
}

// ---------------------------------------------------------------------------
// Flash-style attention, 4 threads per q-row (16 dims each).
// Block = 256 threads = 64 q-rows. Score dot reduced across the lane-quad via
// shfl_xor butterfly (quads are consecutive lanes; softmax state is
// bit-identical within a quad, so no divergence at the shfl).
// mask int32: nonzero -> key excluded. Scale = 1/32.
// ---------------------------------------------------------------------------
__global__ __launch_bounds__(256, 3)
void attn_kernel(const float* __restrict__ Q, const float* __restrict__ Km,
                 const float* __restrict__ Vm,
                 const int* __restrict__ mask,
                 float* __restrict__ O)
{
    __shared__ float4 Ks[64][16];
    __shared__ float4 Vs[64][16];
    __shared__ int ms[64];

    const int tid  = threadIdx.x;
    const int row  = tid >> 2;         // q-row within tile (0..63)
    const int part = tid & 3;          // 16-dim slice (0..3)
    const int qt = blockIdx.x;
    const int h  = blockIdx.y;
    const int b  = blockIdx.z;
    const int hb = h * HD_ + part * 16;
    const int qr = qt * 64 + row;

    const float4* qp = (const float4*)(Q + ((size_t)(b * S_ + qr)) * H_ + hb);
    float4 q[4];
#pragma unroll
    for (int c = 0; c < 4; c++) q[c] = qp[c];

    float4 acc[4];
#pragma unroll
    for (int c = 0; c < 4; c++) acc[c] = make_float4(0.f, 0.f, 0.f, 0.f);
    float mmax = -3.0e38f;
    float l = 0.f;

    for (int kt = 0; kt < S_; kt += 64) {
        const float4* kp = (const float4*)(Km + ((size_t)(b * S_ + kt)) * H_ + h * HD_);
        const float4* vp = (const float4*)(Vm + ((size_t)(b * S_ + kt)) * H_ + h * HD_);
        // 64 rows x 16 float4 each for K and V; 256 threads x 4 slots each.
#pragma unroll
        for (int i = 0; i < 4; i++) {
            int idx = tid + i * 256;
            int r = idx >> 4, c = idx & 15;
            Ks[r][c] = kp[(size_t)r * (H_ / 4) + c];
            Vs[r][c] = vp[(size_t)r * (H_ / 4) + c];
        }
        if (tid < 64) ms[tid] = mask[(size_t)b * S_ + kt + tid];
        __syncthreads();

        for (int kk = 0; kk < 64; kk++) {
            if (ms[kk]) continue;          // block-uniform: warp stays converged
            const float4* krow = &Ks[kk][part * 4];
            float s = 0.f;
#pragma unroll
            for (int c = 0; c < 4; c++) {
                float4 kv = krow[c];
                s += q[c].x * kv.x + q[c].y * kv.y + q[c].z * kv.z + q[c].w * kv.w;
            }
            // quad butterfly: full dot in all 4 lanes of the quad
            s += __shfl_xor_sync(0xffffffffu, s, 1);
            s += __shfl_xor_sync(0xffffffffu, s, 2);
            s *= 0.03125f;

            float p;
            if (s > mmax) {
                float f = __expf(mmax - s);
                l = l * f + 1.f;
#pragma unroll
                for (int c = 0; c < 4; c++) {
                    acc[c].x *= f; acc[c].y *= f; acc[c].z *= f; acc[c].w *= f;
                }
                mmax = s;
                p = 1.f;
            } else {
                p = __expf(s - mmax);
                l += p;
            }
            const float4* vrow = &Vs[kk][part * 4];
#pragma unroll
            for (int c = 0; c < 4; c++) {
                float4 vv = vrow[c];
                acc[c].x += p * vv.x;
                acc[c].y += p * vv.y;
                acc[c].z += p * vv.z;
                acc[c].w += p * vv.w;
            }
        }
        __syncthreads();
    }

    const float rl = 1.f / l;
    float4* op = (float4*)(O + ((size_t)(b * S_ + qr)) * H_ + hb);
#pragma unroll
    for (int c = 0; c < 4; c++) {
        float4 o;
        o.x = acc[c].x * rl;
        o.y = acc[c].y * rl;
        o.z = acc[c].z * rl;
        o.w = acc[c].w * rl;
        op[c] = o;
    }
}

// ---------------------------------------------------------------------------
extern "C" void kernel_launch(void* const* d_in, const int* in_sizes, int n_in,
                              void* d_out, int out_size)
{
    const float* query = (const float*)d_in[0];
    const float* key   = (const float*)d_in[1];
    const float* value = (const float*)d_in[2];
    const int*   mask  = (const int*)d_in[3];

    const int wb = (n_in >= 13) ? 5 : 4;
    const float* Wq = (const float*)d_in[wb + 0];
    const float* bq = (const float*)d_in[wb + 1];
    const float* Wk = (const float*)d_in[wb + 2];
    const float* bk = (const float*)d_in[wb + 3];
    const float* Wv = (const float*)d_in[wb + 4];
    const float* bv = (const float*)d_in[wb + 5];
    const float* Wo = (const float*)d_in[wb + 6];
    const float* bo = (const float*)d_in[wb + 7];
    float* out = (float*)d_out;

    float *dQ, *dK, *dV, *dA;
    cudaGetSymbolAddress((void**)&dQ, g_Q);
    cudaGetSymbolAddress((void**)&dK, g_K);
    cudaGetSymbolAddress((void**)&dV, g_V);
    cudaGetSymbolAddress((void**)&dA, g_A);

    dim3 ggrid(H_ / 128, MROWS / 128);   // (8, 64)
    gemm_tc<<<ggrid, 256>>>(query, Wq, bq, dQ);
    gemm_tc<<<ggrid, 256>>>(key,   Wk, bk, dK);
    gemm_tc<<<ggrid, 256>>>(value, Wv, bv, dV);

    dim3 agrid(S_ / 64, NH_, B_);        // (16, 16, 8)
    attn_kernel<<<agrid, 256>>>(dQ, dK, dV, mask, dA);

    gemm_tc<<<ggrid, 256>>>(dA, Wo, bo, out);
}

// round 6
// speedup vs baseline: 2.6192x; 2.6192x over previous
#include <cuda_runtime.h>
#include <cuda_bf16.h>
#include <cstdint>

#define B_  8
#define S_  1024
#define H_  1024
#define NH_ 16
#define HD_ 64
#define MROWS (B_ * S_)

// Scratch: Q, K, V projections and attention output (each 32 MB).
__device__ float g_Q[MROWS * H_];
__device__ float g_K[MROWS * H_];
__device__ float g_V[MROWS * H_];
__device__ float g_A[MROWS * H_];

__device__ __forceinline__ uint32_t smem_u32(const void* p) {
    uint32_t a;
    asm("{ .reg .u64 t; cvta.to.shared.u64 t, %1; cvt.u32.u64 %0, t; }"
        : "=r"(a) : "l"(p));
    return a;
}

#define LDMX4(r0, r1, r2, r3, addr) \
    asm volatile("ldmatrix.sync.aligned.m8n8.x4.shared.b16 {%0,%1,%2,%3}, [%4];" \
                 : "=r"(r0), "=r"(r1), "=r"(r2), "=r"(r3) : "r"(addr))

#define LDMX4T(r0, r1, r2, r3, addr) \
    asm volatile("ldmatrix.sync.aligned.m8n8.x4.trans.shared.b16 {%0,%1,%2,%3}, [%4];" \
                 : "=r"(r0), "=r"(r1), "=r"(r2), "=r"(r3) : "r"(addr))

#define MMA16816(d, a, b) \
    asm volatile("mma.sync.aligned.m16n8k16.row.col.f32.bf16.bf16.f32 " \
                 "{%0,%1,%2,%3}, {%4,%5,%6,%7}, {%8,%9}, {%0,%1,%2,%3};" \
                 : "+f"((d)[0]), "+f"((d)[1]), "+f"((d)[2]), "+f"((d)[3]) \
                 : "r"((a)[0]), "r"((a)[1]), "r"((a)[2]), "r"((a)[3]), \
                   "r"((b)[0]), "r"((b)[1]))

__device__ __forceinline__ uint32_t pack_hi(float x, float y) {
    __nv_bfloat162 h = __float22bfloat162_rn(make_float2(x, y));
    return *(uint32_t*)&h;
}
__device__ __forceinline__ uint32_t pack_lo(float x, float y, uint32_t hi) {
    __nv_bfloat162 h = *(__nv_bfloat162*)&hi;
    __nv_bfloat162 l = __float22bfloat162_rn(make_float2(
        x - __bfloat162float(h.x), y - __bfloat162float(h.y)));
    return *(uint32_t*)&l;
}

// ===========================================================================
// bf16 mma.sync split-precision GEMM (unchanged from R4, known-good).
// ===========================================================================
#define LDSROW 40

__global__ __launch_bounds__(256, 1)
void gemm_tc(const float* __restrict__ A, const float* __restrict__ W,
             const float* __restrict__ bias, float* __restrict__ C)
{
    __shared__ __nv_bfloat16 sAh[128 * LDSROW];
    __shared__ __nv_bfloat16 sAl[128 * LDSROW];
    __shared__ __nv_bfloat16 sWh[128 * LDSROW];
    __shared__ __nv_bfloat16 sWl[128 * LDSROW];

    const int tid  = threadIdx.x;
    const int wid  = tid >> 5;
    const int lane = tid & 31;
    const int wm   = wid & 1;
    const int wn   = wid >> 1;
    const int bm0  = blockIdx.y * 128;
    const int bn0  = blockIdx.x * 128;

    const uint32_t bAh = smem_u32(sAh);
    const uint32_t bAl = smem_u32(sAl);
    const uint32_t bWh = smem_u32(sWh);
    const uint32_t bWl = smem_u32(sWl);

    const uint32_t aLOff = (uint32_t)((wm * 64 + (lane & 15)) * (LDSROW * 2) + (lane >> 4) * 16);
    const uint32_t bLOff = (uint32_t)((wn * 32 + ((lane >> 4) & 1) * 8 + (lane & 7)) * (LDSROW * 2)
                                      + ((lane >> 3) & 1) * 16);

    int gRow[4], gC4[4];
#pragma unroll
    for (int i = 0; i < 4; i++) { int s = tid + i * 256; gRow[i] = s >> 3; gC4[i] = s & 7; }

    float acc[4][4][4];
#pragma unroll
    for (int mi = 0; mi < 4; mi++)
#pragma unroll
        for (int nj = 0; nj < 4; nj++)
#pragma unroll
            for (int e = 0; e < 4; e++) acc[mi][nj][e] = 0.f;

    float4 ra[4], rw[4];
#pragma unroll
    for (int i = 0; i < 4; i++) {
        ra[i] = *(const float4*)(A + (size_t)(bm0 + gRow[i]) * H_ + gC4[i] * 4);
        rw[i] = *(const float4*)(W + (size_t)(bn0 + gRow[i]) * H_ + gC4[i] * 4);
    }

    for (int c = 0; c < 32; c++) {
#pragma unroll
        for (int i = 0; i < 4; i++) {
            const int off = gRow[i] * LDSROW + gC4[i] * 4;
            float4 a4 = ra[i], w4 = rw[i];
            uint32_t ah01 = pack_hi(a4.x, a4.y), ah23 = pack_hi(a4.z, a4.w);
            *(uint32_t*)(sAh + off)     = ah01;
            *(uint32_t*)(sAh + off + 2) = ah23;
            *(uint32_t*)(sAl + off)     = pack_lo(a4.x, a4.y, ah01);
            *(uint32_t*)(sAl + off + 2) = pack_lo(a4.z, a4.w, ah23);

            uint32_t wh01 = pack_hi(w4.x, w4.y), wh23 = pack_hi(w4.z, w4.w);
            *(uint32_t*)(sWh + off)     = wh01;
            *(uint32_t*)(sWh + off + 2) = wh23;
            *(uint32_t*)(sWl + off)     = pack_lo(w4.x, w4.y, wh01);
            *(uint32_t*)(sWl + off + 2) = pack_lo(w4.z, w4.w, wh23);
        }
        __syncthreads();

        if (c < 31) {
            const int k0 = (c + 1) * 32;
#pragma unroll
            for (int i = 0; i < 4; i++) {
                ra[i] = *(const float4*)(A + (size_t)(bm0 + gRow[i]) * H_ + k0 + gC4[i] * 4);
                rw[i] = *(const float4*)(W + (size_t)(bn0 + gRow[i]) * H_ + k0 + gC4[i] * 4);
            }
        }

#pragma unroll
        for (int ks = 0; ks < 2; ks++) {
            const uint32_t kb = (uint32_t)(ks * 32);
            uint32_t ah[4][4], al[4][4];
#pragma unroll
            for (int mi = 0; mi < 4; mi++) {
                const uint32_t rowb = (uint32_t)(mi * 16 * LDSROW * 2) + aLOff + kb;
                LDMX4(ah[mi][0], ah[mi][1], ah[mi][2], ah[mi][3], bAh + rowb);
                LDMX4(al[mi][0], al[mi][1], al[mi][2], al[mi][3], bAl + rowb);
            }
            uint32_t bh[4][2], bl[4][2];
#pragma unroll
            for (int pr = 0; pr < 2; pr++) {
                const uint32_t rowb = (uint32_t)(pr * 16 * LDSROW * 2) + bLOff + kb;
                LDMX4(bh[pr * 2][0], bh[pr * 2][1], bh[pr * 2 + 1][0], bh[pr * 2 + 1][1], bWh + rowb);
                LDMX4(bl[pr * 2][0], bl[pr * 2][1], bl[pr * 2 + 1][0], bl[pr * 2 + 1][1], bWl + rowb);
            }
#pragma unroll
            for (int mi = 0; mi < 4; mi++)
#pragma unroll
                for (int nj = 0; nj < 4; nj++) {
                    MMA16816(acc[mi][nj], ah[mi], bh[nj]);
                    MMA16816(acc[mi][nj], al[mi], bh[nj]);
                    MMA16816(acc[mi][nj], ah[mi], bl[nj]);
                }
        }
        __syncthreads();
    }

#pragma unroll
    for (int mi = 0; mi < 4; mi++) {
        const int r0 = bm0 + wm * 64 + mi * 16 + (lane >> 2);
#pragma unroll
        for (int nj = 0; nj < 4; nj++) {
            const int col = bn0 + wn * 32 + nj * 8 + (lane & 3) * 2;
            const float b0 = bias[col], b1 = bias[col + 1];
            float2 o0 = make_float2(acc[mi][nj][0] + b0, acc[mi][nj][1] + b1);
            float2 o1 = make_float2(acc[mi][nj][2] + b0, acc[mi][nj][3] + b1);
            *(float2*)(C + (size_t)r0 * H_ + col)       = o0;
            *(float2*)(C + (size_t)(r0 + 8) * H_ + col) = o1;
        }
    }
}

// ===========================================================================
// Tensor-core flash attention. Block = 128 thr (4 warps) per (b,h,64-q-rows).
// Warp: 16 q-rows x 64 keys per tile. S = QK^T and O += P V both via
// 3-term bf16 split mma. Per-tile online softmax in fragments.
// Scale 1/32. mask int32 nonzero -> excluded (explicit p=0).
// ===========================================================================
#define AT_ROW 72          // bf16 per smem row: 64 + 8 pad (144 B)

__global__ __launch_bounds__(128, 2)
void attn_tc(const float* __restrict__ Qm, const float* __restrict__ Km,
             const float* __restrict__ Vm, const int* __restrict__ mask,
             float* __restrict__ O)
{
    __shared__ __nv_bfloat16 sKh[64 * AT_ROW];
    __shared__ __nv_bfloat16 sKl[64 * AT_ROW];
    __shared__ __nv_bfloat16 sVh[64 * AT_ROW];
    __shared__ __nv_bfloat16 sVl[64 * AT_ROW];
    __shared__ uint32_t mbits[2];

    const int tid  = threadIdx.x;
    const int wid  = tid >> 5;
    const int lane = tid & 31;
    const int qt = blockIdx.x;
    const int h  = blockIdx.y;
    const int b  = blockIdx.z;

    const uint32_t bKh = smem_u32(sKh);
    const uint32_t bKl = smem_u32(sKl);
    const uint32_t bVh = smem_u32(sVh);
    const uint32_t bVl = smem_u32(sVl);

    // ---- load Q fragments directly from global (hi/lo split) ----
    const int r0 = wid * 16 + (lane >> 2);          // warp-local q row
    const float* Qb = Qm + ((size_t)(b * S_ + qt * 64)) * H_ + h * HD_;
    uint32_t qh[4][4], ql[4][4];
#pragma unroll
    for (int ks = 0; ks < 4; ks++) {
        const int kb = ks * 16 + (lane & 3) * 2;
        float2 v0 = *(const float2*)(Qb + (size_t)r0 * H_ + kb);
        float2 v1 = *(const float2*)(Qb + (size_t)(r0 + 8) * H_ + kb);
        float2 v2 = *(const float2*)(Qb + (size_t)r0 * H_ + kb + 8);
        float2 v3 = *(const float2*)(Qb + (size_t)(r0 + 8) * H_ + kb + 8);
        qh[ks][0] = pack_hi(v0.x, v0.y);  ql[ks][0] = pack_lo(v0.x, v0.y, qh[ks][0]);
        qh[ks][1] = pack_hi(v1.x, v1.y);  ql[ks][1] = pack_lo(v1.x, v1.y, qh[ks][1]);
        qh[ks][2] = pack_hi(v2.x, v2.y);  ql[ks][2] = pack_lo(v2.x, v2.y, qh[ks][2]);
        qh[ks][3] = pack_hi(v3.x, v3.y);  ql[ks][3] = pack_lo(v3.x, v3.y, qh[ks][3]);
    }

    float oacc[8][4];
#pragma unroll
    for (int nj = 0; nj < 8; nj++)
#pragma unroll
        for (int e = 0; e < 4; e++) oacc[nj][e] = 0.f;
    float m0 = -1e30f, m1 = -1e30f, l0 = 0.f, l1 = 0.f;

    for (int kt = 0; kt < 16; kt++) {
        __syncthreads();
        // ---- stage K/V tile (fp32 -> bf16 hi/lo) ----
        const float* Kp = Km + ((size_t)(b * S_ + kt * 64)) * H_ + h * HD_;
        const float* Vp = Vm + ((size_t)(b * S_ + kt * 64)) * H_ + h * HD_;
#pragma unroll
        for (int i = 0; i < 8; i++) {
            const int slot = tid + i * 128;
            const int r  = slot >> 4;
            const int c4 = slot & 15;
            const int off = r * AT_ROW + c4 * 4;
            float4 kv = *(const float4*)(Kp + (size_t)r * H_ + c4 * 4);
            uint32_t kh01 = pack_hi(kv.x, kv.y), kh23 = pack_hi(kv.z, kv.w);
            *(uint32_t*)(sKh + off)     = kh01;
            *(uint32_t*)(sKh + off + 2) = kh23;
            *(uint32_t*)(sKl + off)     = pack_lo(kv.x, kv.y, kh01);
            *(uint32_t*)(sKl + off + 2) = pack_lo(kv.z, kv.w, kh23);
            float4 vv = *(const float4*)(Vp + (size_t)r * H_ + c4 * 4);
            uint32_t vh01 = pack_hi(vv.x, vv.y), vh23 = pack_hi(vv.z, vv.w);
            *(uint32_t*)(sVh + off)     = vh01;
            *(uint32_t*)(sVh + off + 2) = vh23;
            *(uint32_t*)(sVl + off)     = pack_lo(vv.x, vv.y, vh01);
            *(uint32_t*)(sVl + off + 2) = pack_lo(vv.z, vv.w, vh23);
        }
        if (wid == 0) {
            int mv0 = mask[(size_t)b * S_ + kt * 64 + lane];
            unsigned b0v = __ballot_sync(0xffffffffu, mv0 != 0);
            int mv1 = mask[(size_t)b * S_ + kt * 64 + 32 + lane];
            unsigned b1v = __ballot_sync(0xffffffffu, mv1 != 0);
            if (lane == 0) { mbits[0] = b0v; mbits[1] = b1v; }
        }
        __syncthreads();
        const uint32_t mw0 = mbits[0], mw1 = mbits[1];

        // ---- S = Q K^T (3-term split) ----
        float sacc[8][4];
#pragma unroll
        for (int nj = 0; nj < 8; nj++)
#pragma unroll
            for (int e = 0; e < 4; e++) sacc[nj][e] = 0.f;

#pragma unroll
        for (int ks = 0; ks < 4; ks++) {
            uint32_t bh[8][2], bl[8][2];
#pragma unroll
            for (int g = 0; g < 4; g++) {
                const uint32_t rowb =
                    (uint32_t)((g * 16 + ((lane >> 4) & 1) * 8 + (lane & 7)) * (AT_ROW * 2)
                               + ks * 32 + ((lane >> 3) & 1) * 16);
                LDMX4(bh[2 * g][0], bh[2 * g][1], bh[2 * g + 1][0], bh[2 * g + 1][1], bKh + rowb);
                LDMX4(bl[2 * g][0], bl[2 * g][1], bl[2 * g + 1][0], bl[2 * g + 1][1], bKl + rowb);
            }
#pragma unroll
            for (int nj = 0; nj < 8; nj++) {
                MMA16816(sacc[nj], qh[ks], bh[nj]);
                MMA16816(sacc[nj], ql[ks], bh[nj]);
                MMA16816(sacc[nj], qh[ks], bl[nj]);
            }
        }

        // ---- per-tile softmax on fragments ----
        const int shb = (lane & 3) * 2;
        float mx0 = -1e30f, mx1 = -1e30f;
#pragma unroll
        for (int nj = 0; nj < 8; nj++) {
            const uint32_t w = (nj < 4) ? mw0 : mw1;
            const int sh = (nj & 3) * 8 + shb;
            const bool k0 = (w >> sh) & 1;
            const bool k1 = (w >> (sh + 1)) & 1;
            float s0 = k0 ? -1e30f : sacc[nj][0] * 0.03125f;
            float s1 = k1 ? -1e30f : sacc[nj][1] * 0.03125f;
            float s2 = k0 ? -1e30f : sacc[nj][2] * 0.03125f;
            float s3 = k1 ? -1e30f : sacc[nj][3] * 0.03125f;
            sacc[nj][0] = s0; sacc[nj][1] = s1; sacc[nj][2] = s2; sacc[nj][3] = s3;
            mx0 = fmaxf(mx0, fmaxf(s0, s1));
            mx1 = fmaxf(mx1, fmaxf(s2, s3));
        }
        mx0 = fmaxf(mx0, __shfl_xor_sync(0xffffffffu, mx0, 1));
        mx0 = fmaxf(mx0, __shfl_xor_sync(0xffffffffu, mx0, 2));
        mx1 = fmaxf(mx1, __shfl_xor_sync(0xffffffffu, mx1, 1));
        mx1 = fmaxf(mx1, __shfl_xor_sync(0xffffffffu, mx1, 2));

        const float nm0 = fmaxf(m0, mx0);
        const float nm1 = fmaxf(m1, mx1);
        const float f0 = __expf(m0 - nm0);
        const float f1 = __expf(m1 - nm1);
        m0 = nm0; m1 = nm1;
        l0 *= f0;  l1 *= f1;
#pragma unroll
        for (int nj = 0; nj < 8; nj++) {
            oacc[nj][0] *= f0; oacc[nj][1] *= f0;
            oacc[nj][2] *= f1; oacc[nj][3] *= f1;
        }

        uint32_t pHa[8], pHb[8], pLa[8], pLb[8];
        float ps0 = 0.f, ps1 = 0.f;
#pragma unroll
        for (int nj = 0; nj < 8; nj++) {
            const uint32_t w = (nj < 4) ? mw0 : mw1;
            const int sh = (nj & 3) * 8 + shb;
            const bool k0 = (w >> sh) & 1;
            const bool k1 = (w >> (sh + 1)) & 1;
            float p0 = k0 ? 0.f : __expf(sacc[nj][0] - nm0);
            float p1 = k1 ? 0.f : __expf(sacc[nj][1] - nm0);
            float p2 = k0 ? 0.f : __expf(sacc[nj][2] - nm1);
            float p3 = k1 ? 0.f : __expf(sacc[nj][3] - nm1);
            ps0 += p0 + p1;
            ps1 += p2 + p3;
            pHa[nj] = pack_hi(p0, p1);  pLa[nj] = pack_lo(p0, p1, pHa[nj]);
            pHb[nj] = pack_hi(p2, p3);  pLb[nj] = pack_lo(p2, p3, pHb[nj]);
        }
        l0 += ps0;
        l1 += ps1;

        // ---- O += P V (3-term split); V frags via ldmatrix.x4.trans ----
#pragma unroll
        for (int kk = 0; kk < 4; kk++) {
            uint32_t aH[4] = { pHa[2 * kk], pHb[2 * kk], pHa[2 * kk + 1], pHb[2 * kk + 1] };
            uint32_t aL[4] = { pLa[2 * kk], pLb[2 * kk], pLa[2 * kk + 1], pLb[2 * kk + 1] };
#pragma unroll
            for (int njp = 0; njp < 8; njp += 2) {
                const uint32_t rowb =
                    (uint32_t)((kk * 16 + (lane & 15)) * (AT_ROW * 2)
                               + (njp + ((lane >> 4) & 1)) * 16);
                uint32_t vh[2][2], vl[2][2];
                LDMX4T(vh[0][0], vh[0][1], vh[1][0], vh[1][1], bVh + rowb);
                LDMX4T(vl[0][0], vl[0][1], vl[1][0], vl[1][1], bVl + rowb);
                MMA16816(oacc[njp],     aH, vh[0]);
                MMA16816(oacc[njp],     aL, vh[0]);
                MMA16816(oacc[njp],     aH, vl[0]);
                MMA16816(oacc[njp + 1], aH, vh[1]);
                MMA16816(oacc[njp + 1], aL, vh[1]);
                MMA16816(oacc[njp + 1], aH, vl[1]);
            }
        }
    }

    // ---- finalize: reduce l over lane-quad, scale, store ----
    l0 += __shfl_xor_sync(0xffffffffu, l0, 1);
    l0 += __shfl_xor_sync(0xffffffffu, l0, 2);
    l1 += __shfl_xor_sync(0xffffffffu, l1, 1);
    l1 += __shfl_xor_sync(0xffffffffu, l1, 2);
    const float rl0 = 1.f / l0;
    const float rl1 = 1.f / l1;

    float* Ob = O + ((size_t)(b * S_ + qt * 64)) * H_ + h * HD_;
#pragma unroll
    for (int nj = 0; nj < 8; nj++) {
        const int colb = nj * 8 + (lane & 3) * 2;
        *(float2*)(Ob + (size_t)r0 * H_ + colb) =
            make_float2(oacc[nj][0] * rl0, oacc[nj][1] * rl0);
        *(float2*)(Ob + (size_t)(r0 + 8) * H_ + colb) =
            make_float2(oacc[nj][2] * rl1, oacc[nj][3] * rl1);
    }
}

// ---------------------------------------------------------------------------
extern "C" void kernel_launch(void* const* d_in, const int* in_sizes, int n_in,
                              void* d_out, int out_size)
{
    const float* query = (const float*)d_in[0];
    const float* key   = (const float*)d_in[1];
    const float* value = (const float*)d_in[2];
    const int*   mask  = (const int*)d_in[3];

    const int wb = (n_in >= 13) ? 5 : 4;
    const float* Wq = (const float*)d_in[wb + 0];
    const float* bq = (const float*)d_in[wb + 1];
    const float* Wk = (const float*)d_in[wb + 2];
    const float* bk = (const float*)d_in[wb + 3];
    const float* Wv = (const float*)d_in[wb + 4];
    const float* bv = (const float*)d_in[wb + 5];
    const float* Wo = (const float*)d_in[wb + 6];
    const float* bo = (const float*)d_in[wb + 7];
    float* out = (float*)d_out;

    float *dQ, *dK, *dV, *dA;
    cudaGetSymbolAddress((void**)&dQ, g_Q);
    cudaGetSymbolAddress((void**)&dK, g_K);
    cudaGetSymbolAddress((void**)&dV, g_V);
    cudaGetSymbolAddress((void**)&dA, g_A);

    dim3 ggrid(H_ / 128, MROWS / 128);   // (8, 64)
    gemm_tc<<<ggrid, 256>>>(query, Wq, bq, dQ);
    gemm_tc<<<ggrid, 256>>>(key,   Wk, bk, dK);
    gemm_tc<<<ggrid, 256>>>(value, Wv, bv, dV);

    dim3 agrid(S_ / 64, NH_, B_);        // (16, 16, 8)
    attn_tc<<<agrid, 128>>>(dQ, dK, dV, mask, dA);

    gemm_tc<<<ggrid, 256>>>(dA, Wo, bo, out);
}

// round 7
// speedup vs baseline: 2.9461x; 1.1248x over previous
#include <cuda_runtime.h>
#include <cuda_bf16.h>
#include <cstdint>

#define B_  8
#define S_  1024
#define H_  1024
#define NH_ 16
#define HD_ 64
#define MROWS (B_ * S_)

// Scratch: Q, K, V projections and attention output (each 32 MB).
__device__ float g_Q[MROWS * H_];
__device__ float g_K[MROWS * H_];
__device__ float g_V[MROWS * H_];
__device__ float g_A[MROWS * H_];

__device__ __forceinline__ uint32_t smem_u32(const void* p) {
    uint32_t a;
    asm("{ .reg .u64 t; cvta.to.shared.u64 t, %1; cvt.u32.u64 %0, t; }"
        : "=r"(a) : "l"(p));
    return a;
}

#define LDMX4(r0, r1, r2, r3, addr) \
    asm volatile("ldmatrix.sync.aligned.m8n8.x4.shared.b16 {%0,%1,%2,%3}, [%4];" \
                 : "=r"(r0), "=r"(r1), "=r"(r2), "=r"(r3) : "r"(addr))

#define LDMX4T(r0, r1, r2, r3, addr) \
    asm volatile("ldmatrix.sync.aligned.m8n8.x4.trans.shared.b16 {%0,%1,%2,%3}, [%4];" \
                 : "=r"(r0), "=r"(r1), "=r"(r2), "=r"(r3) : "r"(addr))

#define MMA16816(d, a, b) \
    asm volatile("mma.sync.aligned.m16n8k16.row.col.f32.bf16.bf16.f32 " \
                 "{%0,%1,%2,%3}, {%4,%5,%6,%7}, {%8,%9}, {%0,%1,%2,%3};" \
                 : "+f"((d)[0]), "+f"((d)[1]), "+f"((d)[2]), "+f"((d)[3]) \
                 : "r"((a)[0]), "r"((a)[1]), "r"((a)[2]), "r"((a)[3]), \
                   "r"((b)[0]), "r"((b)[1]))

__device__ __forceinline__ uint32_t pack_hi(float x, float y) {
    __nv_bfloat162 h = __float22bfloat162_rn(make_float2(x, y));
    return *(uint32_t*)&h;
}
__device__ __forceinline__ uint32_t pack_lo(float x, float y, uint32_t hi) {
    __nv_bfloat162 h = *(__nv_bfloat162*)&hi;
    __nv_bfloat162 l = __float22bfloat162_rn(make_float2(
        x - __bfloat162float(h.x), y - __bfloat162float(h.y)));
    return *(uint32_t*)&l;
}

// ===========================================================================
// bf16 mma.sync split-precision GEMM, double-buffered (one sync per chunk).
// C[m,n] = sum_k A[m,k]*W[n,k] + bias[n]; 128x128 tile, BK=32, 8 warps.
// ===========================================================================
#define LDSROW 40
#define GOP_ELEMS   (128 * LDSROW)          // 5120 bf16 per operand tile
#define GSTAGE_ELEMS (4 * GOP_ELEMS)        // Ah, Al, Wh, Wl
#define GSTAGE_BYTES (GSTAGE_ELEMS * 2)     // 40960
#define GEMM_SMEM    (2 * GSTAGE_BYTES)     // 81920

__global__ __launch_bounds__(256, 1)
void gemm_tc(const float* __restrict__ A, const float* __restrict__ W,
             const float* __restrict__ bias, float* __restrict__ C)
{
    extern __shared__ __nv_bfloat16 gsm[];

    const int tid  = threadIdx.x;
    const int wid  = tid >> 5;
    const int lane = tid & 31;
    const int wm   = wid & 1;
    const int wn   = wid >> 1;
    const int bm0  = blockIdx.y * 128;
    const int bn0  = blockIdx.x * 128;

    const uint32_t ubase = smem_u32(gsm);

    const uint32_t aLOff = (uint32_t)((wm * 64 + (lane & 15)) * (LDSROW * 2) + (lane >> 4) * 16);
    const uint32_t bLOff = (uint32_t)((wn * 32 + ((lane >> 4) & 1) * 8 + (lane & 7)) * (LDSROW * 2)
                                      + ((lane >> 3) & 1) * 16);

    int gRow[4], gC4[4];
#pragma unroll
    for (int i = 0; i < 4; i++) { int s = tid + i * 256; gRow[i] = s >> 3; gC4[i] = s & 7; }

    float acc[4][4][4];
#pragma unroll
    for (int mi = 0; mi < 4; mi++)
#pragma unroll
        for (int nj = 0; nj < 4; nj++)
#pragma unroll
            for (int e = 0; e < 4; e++) acc[mi][nj][e] = 0.f;

    float4 ra[4], rw[4];
#pragma unroll
    for (int i = 0; i < 4; i++) {
        ra[i] = *(const float4*)(A + (size_t)(bm0 + gRow[i]) * H_ + gC4[i] * 4);
        rw[i] = *(const float4*)(W + (size_t)(bn0 + gRow[i]) * H_ + gC4[i] * 4);
    }

    for (int c = 0; c < 32; c++) {
        const int sel = c & 1;
        // ---- stage chunk c (regs -> smem buf[sel]) ----
        __nv_bfloat16* st = gsm + sel * GSTAGE_ELEMS;
#pragma unroll
        for (int i = 0; i < 4; i++) {
            const int off = gRow[i] * LDSROW + gC4[i] * 4;
            float4 a4 = ra[i], w4 = rw[i];
            uint32_t ah01 = pack_hi(a4.x, a4.y), ah23 = pack_hi(a4.z, a4.w);
            *(uint32_t*)(st + off)     = ah01;
            *(uint32_t*)(st + off + 2) = ah23;
            *(uint32_t*)(st + GOP_ELEMS + off)     = pack_lo(a4.x, a4.y, ah01);
            *(uint32_t*)(st + GOP_ELEMS + off + 2) = pack_lo(a4.z, a4.w, ah23);

            uint32_t wh01 = pack_hi(w4.x, w4.y), wh23 = pack_hi(w4.z, w4.w);
            *(uint32_t*)(st + 2 * GOP_ELEMS + off)     = wh01;
            *(uint32_t*)(st + 2 * GOP_ELEMS + off + 2) = wh23;
            *(uint32_t*)(st + 3 * GOP_ELEMS + off)     = pack_lo(w4.x, w4.y, wh01);
            *(uint32_t*)(st + 3 * GOP_ELEMS + off + 2) = pack_lo(w4.z, w4.w, wh23);
        }
        __syncthreads();

        // prefetch next chunk
        if (c < 31) {
            const int k0 = (c + 1) * 32;
#pragma unroll
            for (int i = 0; i < 4; i++) {
                ra[i] = *(const float4*)(A + (size_t)(bm0 + gRow[i]) * H_ + k0 + gC4[i] * 4);
                rw[i] = *(const float4*)(W + (size_t)(bn0 + gRow[i]) * H_ + k0 + gC4[i] * 4);
            }
        }

        // ---- compute from buf[sel] ----
        const uint32_t ub  = ubase + (uint32_t)sel * GSTAGE_BYTES;
        const uint32_t bAh = ub;
        const uint32_t bAl = ub + GOP_ELEMS * 2;
        const uint32_t bWh = ub + 2 * GOP_ELEMS * 2;
        const uint32_t bWl = ub + 3 * GOP_ELEMS * 2;
#pragma unroll
        for (int ks = 0; ks < 2; ks++) {
            const uint32_t kb = (uint32_t)(ks * 32);
            uint32_t ah[4][4], al[4][4];
#pragma unroll
            for (int mi = 0; mi < 4; mi++) {
                const uint32_t rowb = (uint32_t)(mi * 16 * LDSROW * 2) + aLOff + kb;
                LDMX4(ah[mi][0], ah[mi][1], ah[mi][2], ah[mi][3], bAh + rowb);
                LDMX4(al[mi][0], al[mi][1], al[mi][2], al[mi][3], bAl + rowb);
            }
            uint32_t bh[4][2], bl[4][2];
#pragma unroll
            for (int pr = 0; pr < 2; pr++) {
                const uint32_t rowb = (uint32_t)(pr * 16 * LDSROW * 2) + bLOff + kb;
                LDMX4(bh[pr * 2][0], bh[pr * 2][1], bh[pr * 2 + 1][0], bh[pr * 2 + 1][1], bWh + rowb);
                LDMX4(bl[pr * 2][0], bl[pr * 2][1], bl[pr * 2 + 1][0], bl[pr * 2 + 1][1], bWl + rowb);
            }
#pragma unroll
            for (int mi = 0; mi < 4; mi++)
#pragma unroll
                for (int nj = 0; nj < 4; nj++) {
                    MMA16816(acc[mi][nj], ah[mi], bh[nj]);
                    MMA16816(acc[mi][nj], al[mi], bh[nj]);
                    MMA16816(acc[mi][nj], ah[mi], bl[nj]);
                }
        }
    }

#pragma unroll
    for (int mi = 0; mi < 4; mi++) {
        const int r0 = bm0 + wm * 64 + mi * 16 + (lane >> 2);
#pragma unroll
        for (int nj = 0; nj < 4; nj++) {
            const int col = bn0 + wn * 32 + nj * 8 + (lane & 3) * 2;
            const float b0 = bias[col], b1 = bias[col + 1];
            float2 o0 = make_float2(acc[mi][nj][0] + b0, acc[mi][nj][1] + b1);
            float2 o1 = make_float2(acc[mi][nj][2] + b0, acc[mi][nj][3] + b1);
            *(float2*)(C + (size_t)r0 * H_ + col)       = o0;
            *(float2*)(C + (size_t)(r0 + 8) * H_ + col) = o1;
        }
    }
}

// ===========================================================================
// Tensor-core flash attention, BQ=128 (8 warps), double-buffered K/V with
// register prefetch; one sync per key-tile. Per-tile softmax in fragments.
// Scale 1/32. mask int32 nonzero -> excluded.
// ===========================================================================
#define AT_ROW 72
#define AT_OP_ELEMS (64 * AT_ROW)             // 4608 bf16 per operand
#define AT_STAGE_ELEMS (4 * AT_OP_ELEMS)      // Kh, Kl, Vh, Vl
#define AT_STAGE_BYTES (AT_STAGE_ELEMS * 2)   // 36864
#define ATTN_SMEM (2 * AT_STAGE_BYTES)        // 73728

__device__ __forceinline__ void attn_load_kv(
    const float* Kp, const float* Vp, int tid, float4* kn, float4* vn)
{
#pragma unroll
    for (int i = 0; i < 4; i++) {
        const int slot = tid + i * 256;
        const int r  = slot >> 4;
        const int c4 = slot & 15;
        kn[i] = *(const float4*)(Kp + (size_t)r * H_ + c4 * 4);
        vn[i] = *(const float4*)(Vp + (size_t)r * H_ + c4 * 4);
    }
}

__device__ __forceinline__ void attn_stage_kv(
    __nv_bfloat16* st, int tid, const float4* kn, const float4* vn)
{
#pragma unroll
    for (int i = 0; i < 4; i++) {
        const int slot = tid + i * 256;
        const int r  = slot >> 4;
        const int c4 = slot & 15;
        const int off = r * AT_ROW + c4 * 4;
        float4 kv = kn[i];
        uint32_t kh01 = pack_hi(kv.x, kv.y), kh23 = pack_hi(kv.z, kv.w);
        *(uint32_t*)(st + off)     = kh01;
        *(uint32_t*)(st + off + 2) = kh23;
        *(uint32_t*)(st + AT_OP_ELEMS + off)     = pack_lo(kv.x, kv.y, kh01);
        *(uint32_t*)(st + AT_OP_ELEMS + off + 2) = pack_lo(kv.z, kv.w, kh23);
        float4 vv = vn[i];
        uint32_t vh01 = pack_hi(vv.x, vv.y), vh23 = pack_hi(vv.z, vv.w);
        *(uint32_t*)(st + 2 * AT_OP_ELEMS + off)     = vh01;
        *(uint32_t*)(st + 2 * AT_OP_ELEMS + off + 2) = vh23;
        *(uint32_t*)(st + 3 * AT_OP_ELEMS + off)     = pack_lo(vv.x, vv.y, vh01);
        *(uint32_t*)(st + 3 * AT_OP_ELEMS + off + 2) = pack_lo(vv.z, vv.w, vh23);
    }
}

__global__ __launch_bounds__(256, 1)
void attn_tc(const float* __restrict__ Qm, const float* __restrict__ Km,
             const float* __restrict__ Vm, const int* __restrict__ mask,
             float* __restrict__ O)
{
    extern __shared__ __nv_bfloat16 asmem[];
    __shared__ uint32_t mbits[2][2];

    const int tid  = threadIdx.x;
    const int wid  = tid >> 5;           // 0..7
    const int lane = tid & 31;
    const int qt = blockIdx.x;           // 8 tiles of 128 q-rows
    const int h  = blockIdx.y;
    const int b  = blockIdx.z;

    const uint32_t ubase = smem_u32(asmem);

    // ---- Q fragments (hi/lo) straight from global ----
    const int r0 = wid * 16 + (lane >> 2);          // row within 128-row tile
    const float* Qb = Qm + ((size_t)(b * S_ + qt * 128)) * H_ + h * HD_;
    uint32_t qh[4][4], ql[4][4];
#pragma unroll
    for (int ks = 0; ks < 4; ks++) {
        const int kb = ks * 16 + (lane & 3) * 2;
        float2 v0 = *(const float2*)(Qb + (size_t)r0 * H_ + kb);
        float2 v1 = *(const float2*)(Qb + (size_t)(r0 + 8) * H_ + kb);
        float2 v2 = *(const float2*)(Qb + (size_t)r0 * H_ + kb + 8);
        float2 v3 = *(const float2*)(Qb + (size_t)(r0 + 8) * H_ + kb + 8);
        qh[ks][0] = pack_hi(v0.x, v0.y);  ql[ks][0] = pack_lo(v0.x, v0.y, qh[ks][0]);
        qh[ks][1] = pack_hi(v1.x, v1.y);  ql[ks][1] = pack_lo(v1.x, v1.y, qh[ks][1]);
        qh[ks][2] = pack_hi(v2.x, v2.y);  ql[ks][2] = pack_lo(v2.x, v2.y, qh[ks][2]);
        qh[ks][3] = pack_hi(v3.x, v3.y);  ql[ks][3] = pack_lo(v3.x, v3.y, qh[ks][3]);
    }

    float oacc[8][4];
#pragma unroll
    for (int nj = 0; nj < 8; nj++)
#pragma unroll
        for (int e = 0; e < 4; e++) oacc[nj][e] = 0.f;
    float m0 = -1e30f, m1 = -1e30f, l0 = 0.f, l1 = 0.f;

    const float* Kb = Km + ((size_t)b * S_) * H_ + h * HD_;
    const float* Vb = Vm + ((size_t)b * S_) * H_ + h * HD_;

    // ---- prologue: load + stage tile 0 ----
    float4 kn[4], vn[4];
    attn_load_kv(Kb, Vb, tid, kn, vn);
    attn_stage_kv(asmem, tid, kn, vn);
    int mv0 = 0, mv1 = 0;
    if (wid == 0) {
        mv0 = mask[(size_t)b * S_ + lane];
        mv1 = mask[(size_t)b * S_ + 32 + lane];
        unsigned b0v = __ballot_sync(0xffffffffu, mv0 != 0);
        unsigned b1v = __ballot_sync(0xffffffffu, mv1 != 0);
        if (lane == 0) { mbits[0][0] = b0v; mbits[0][1] = b1v; }
    }

    for (int kt = 0; kt < 16; kt++) {
        const int sel = kt & 1;
        __syncthreads();                 // staging of buf[sel] complete
        const uint32_t mw0 = mbits[sel][0];
        const uint32_t mw1 = mbits[sel][1];
        const uint32_t ub  = ubase + (uint32_t)sel * AT_STAGE_BYTES;
        const uint32_t bKh = ub;
        const uint32_t bKl = ub + AT_OP_ELEMS * 2;
        const uint32_t bVh = ub + 2 * AT_OP_ELEMS * 2;
        const uint32_t bVl = ub + 3 * AT_OP_ELEMS * 2;

        // ---- S = Q K^T (3-term split) ----
        float sacc[8][4];
#pragma unroll
        for (int nj = 0; nj < 8; nj++)
#pragma unroll
            for (int e = 0; e < 4; e++) sacc[nj][e] = 0.f;

#pragma unroll
        for (int ks = 0; ks < 4; ks++) {
            uint32_t bh[8][2], bl[8][2];
#pragma unroll
            for (int g = 0; g < 4; g++) {
                const uint32_t rowb =
                    (uint32_t)((g * 16 + ((lane >> 4) & 1) * 8 + (lane & 7)) * (AT_ROW * 2)
                               + ks * 32 + ((lane >> 3) & 1) * 16);
                LDMX4(bh[2 * g][0], bh[2 * g][1], bh[2 * g + 1][0], bh[2 * g + 1][1], bKh + rowb);
                LDMX4(bl[2 * g][0], bl[2 * g][1], bl[2 * g + 1][0], bl[2 * g + 1][1], bKl + rowb);
            }
#pragma unroll
            for (int nj = 0; nj < 8; nj++) {
                MMA16816(sacc[nj], qh[ks], bh[nj]);
                MMA16816(sacc[nj], ql[ks], bh[nj]);
                MMA16816(sacc[nj], qh[ks], bl[nj]);
            }
        }

        // ---- prefetch next K/V tile + mask (global -> regs) ----
        if (kt < 15) {
            attn_load_kv(Kb + (size_t)(kt + 1) * 64 * H_,
                         Vb + (size_t)(kt + 1) * 64 * H_, tid, kn, vn);
            if (wid == 0) {
                mv0 = mask[(size_t)b * S_ + (kt + 1) * 64 + lane];
                mv1 = mask[(size_t)b * S_ + (kt + 1) * 64 + 32 + lane];
            }
        }

        // ---- per-tile softmax on fragments ----
        const int shb = (lane & 3) * 2;
        float mx0 = -1e30f, mx1 = -1e30f;
#pragma unroll
        for (int nj = 0; nj < 8; nj++) {
            const uint32_t w = (nj < 4) ? mw0 : mw1;
            const int sh = (nj & 3) * 8 + shb;
            const bool k0 = (w >> sh) & 1;
            const bool k1 = (w >> (sh + 1)) & 1;
            float s0 = k0 ? -1e30f : sacc[nj][0] * 0.03125f;
            float s1 = k1 ? -1e30f : sacc[nj][1] * 0.03125f;
            float s2 = k0 ? -1e30f : sacc[nj][2] * 0.03125f;
            float s3 = k1 ? -1e30f : sacc[nj][3] * 0.03125f;
            sacc[nj][0] = s0; sacc[nj][1] = s1; sacc[nj][2] = s2; sacc[nj][3] = s3;
            mx0 = fmaxf(mx0, fmaxf(s0, s1));
            mx1 = fmaxf(mx1, fmaxf(s2, s3));
        }
        mx0 = fmaxf(mx0, __shfl_xor_sync(0xffffffffu, mx0, 1));
        mx0 = fmaxf(mx0, __shfl_xor_sync(0xffffffffu, mx0, 2));
        mx1 = fmaxf(mx1, __shfl_xor_sync(0xffffffffu, mx1, 1));
        mx1 = fmaxf(mx1, __shfl_xor_sync(0xffffffffu, mx1, 2));

        const float nm0 = fmaxf(m0, mx0);
        const float nm1 = fmaxf(m1, mx1);
        const float f0 = __expf(m0 - nm0);
        const float f1 = __expf(m1 - nm1);
        m0 = nm0; m1 = nm1;
        l0 *= f0;  l1 *= f1;
#pragma unroll
        for (int nj = 0; nj < 8; nj++) {
            oacc[nj][0] *= f0; oacc[nj][1] *= f0;
            oacc[nj][2] *= f1; oacc[nj][3] *= f1;
        }

        uint32_t pHa[8], pHb[8], pLa[8], pLb[8];
        float ps0 = 0.f, ps1 = 0.f;
#pragma unroll
        for (int nj = 0; nj < 8; nj++) {
            float p0 = __expf(sacc[nj][0] - nm0);
            float p1 = __expf(sacc[nj][1] - nm0);
            float p2 = __expf(sacc[nj][2] - nm1);
            float p3 = __expf(sacc[nj][3] - nm1);
            ps0 += p0 + p1;
            ps1 += p2 + p3;
            pHa[nj] = pack_hi(p0, p1);  pLa[nj] = pack_lo(p0, p1, pHa[nj]);
            pHb[nj] = pack_hi(p2, p3);  pLb[nj] = pack_lo(p2, p3, pHb[nj]);
        }
        l0 += ps0;
        l1 += ps1;

        // ---- O += P V (3-term split) ----
#pragma unroll
        for (int kk = 0; kk < 4; kk++) {
            uint32_t aH[4] = { pHa[2 * kk], pHb[2 * kk], pHa[2 * kk + 1], pHb[2 * kk + 1] };
            uint32_t aL[4] = { pLa[2 * kk], pLb[2 * kk], pLa[2 * kk + 1], pLb[2 * kk + 1] };
#pragma unroll
            for (int njp = 0; njp < 8; njp += 2) {
                const uint32_t rowb =
                    (uint32_t)((kk * 16 + (lane & 15)) * (AT_ROW * 2)
                               + (njp + ((lane >> 4) & 1)) * 16);
                uint32_t vh[2][2], vl[2][2];
                LDMX4T(vh[0][0], vh[0][1], vh[1][0], vh[1][1], bVh + rowb);
                LDMX4T(vl[0][0], vl[0][1], vl[1][0], vl[1][1], bVl + rowb);
                MMA16816(oacc[njp],     aH, vh[0]);
                MMA16816(oacc[njp],     aL, vh[0]);
                MMA16816(oacc[njp],     aH, vl[0]);
                MMA16816(oacc[njp + 1], aH, vh[1]);
                MMA16816(oacc[njp + 1], aL, vh[1]);
                MMA16816(oacc[njp + 1], aH, vl[1]);
            }
        }

        // ---- stage next tile into other buffer ----
        if (kt < 15) {
            attn_stage_kv(asmem + (sel ^ 1) * AT_STAGE_ELEMS, tid, kn, vn);
            if (wid == 0) {
                unsigned b0v = __ballot_sync(0xffffffffu, mv0 != 0);
                unsigned b1v = __ballot_sync(0xffffffffu, mv1 != 0);
                if (lane == 0) { mbits[sel ^ 1][0] = b0v; mbits[sel ^ 1][1] = b1v; }
            }
        }
    }

    // ---- finalize ----
    l0 += __shfl_xor_sync(0xffffffffu, l0, 1);
    l0 += __shfl_xor_sync(0xffffffffu, l0, 2);
    l1 += __shfl_xor_sync(0xffffffffu, l1, 1);
    l1 += __shfl_xor_sync(0xffffffffu, l1, 2);
    const float rl0 = 1.f / l0;
    const float rl1 = 1.f / l1;

    float* Ob = O + ((size_t)(b * S_ + qt * 128)) * H_ + h * HD_;
#pragma unroll
    for (int nj = 0; nj < 8; nj++) {
        const int colb = nj * 8 + (lane & 3) * 2;
        *(float2*)(Ob + (size_t)r0 * H_ + colb) =
            make_float2(oacc[nj][0] * rl0, oacc[nj][1] * rl0);
        *(float2*)(Ob + (size_t)(r0 + 8) * H_ + colb) =
            make_float2(oacc[nj][2] * rl1, oacc[nj][3] * rl1);
    }
}

// ---------------------------------------------------------------------------
extern "C" void kernel_launch(void* const* d_in, const int* in_sizes, int n_in,
                              void* d_out, int out_size)
{
    const float* query = (const float*)d_in[0];
    const float* key   = (const float*)d_in[1];
    const float* value = (const float*)d_in[2];
    const int*   mask  = (const int*)d_in[3];

    const int wb = (n_in >= 13) ? 5 : 4;
    const float* Wq = (const float*)d_in[wb + 0];
    const float* bq = (const float*)d_in[wb + 1];
    const float* Wk = (const float*)d_in[wb + 2];
    const float* bk = (const float*)d_in[wb + 3];
    const float* Wv = (const float*)d_in[wb + 4];
    const float* bv = (const float*)d_in[wb + 5];
    const float* Wo = (const float*)d_in[wb + 6];
    const float* bo = (const float*)d_in[wb + 7];
    float* out = (float*)d_out;

    float *dQ, *dK, *dV, *dA;
    cudaGetSymbolAddress((void**)&dQ, g_Q);
    cudaGetSymbolAddress((void**)&dK, g_K);
    cudaGetSymbolAddress((void**)&dV, g_V);
    cudaGetSymbolAddress((void**)&dA, g_A);

    cudaFuncSetAttribute(gemm_tc, cudaFuncAttributeMaxDynamicSharedMemorySize, GEMM_SMEM);
    cudaFuncSetAttribute(attn_tc, cudaFuncAttributeMaxDynamicSharedMemorySize, ATTN_SMEM);

    dim3 ggrid(H_ / 128, MROWS / 128);   // (8, 64)
    gemm_tc<<<ggrid, 256, GEMM_SMEM>>>(query, Wq, bq, dQ);
    gemm_tc<<<ggrid, 256, GEMM_SMEM>>>(key,   Wk, bk, dK);
    gemm_tc<<<ggrid, 256, GEMM_SMEM>>>(value, Wv, bv, dV);

    dim3 agrid(S_ / 128, NH_, B_);       // (8, 16, 8)
    attn_tc<<<agrid, 256, ATTN_SMEM>>>(dQ, dK, dV, mask, dA);

    gemm_tc<<<ggrid, 256, GEMM_SMEM>>>(dA, Wo, bo, out);
}